// round 3
// baseline (speedup 1.0000x reference)
#include <cuda_runtime.h>
#include <cstdint>

#define N_NODES 100000
#define FEAT 64
#define OUT_DIM 2

// Per-node projected message m = h @ W1  (L2-resident: 800 KB)
__device__ float2 g_m[N_NODES];

// ---------------------------------------------------------------------------
// Fused kernel: per-block weight fold (into smem) + node projection.
//   W1 = W_rel @ W_pred, W2 = W_root @ W_pred, bias = b_rel@W_pred + b_pred
//   m[i]   = h[i] @ W1        (g_m)
//   out[i] = h[i] @ W2 + bias (root term initializes output)
// Node phase: 4 nodes per warp, 8 lanes per node, float4 loads.
// ---------------------------------------------------------------------------
__global__ __launch_bounds__(1024)
void node_kernel(const float* __restrict__ pos,
                 const float* __restrict__ vel,
                 const float* __restrict__ W_rel,
                 const float* __restrict__ b_rel,
                 const float* __restrict__ W_root,
                 const float* __restrict__ W_pred,
                 const float* __restrict__ b_pred,
                 float* __restrict__ out) {
    __shared__ float2 sW1[FEAT];   // sW1[f] = (W1[f][0], W1[f][1])
    __shared__ float2 sW2[FEAT];
    __shared__ float2 sbias;

    int t = threadIdx.x;

    // ---- fold phase: 258 threads compute the folded weights redundantly ----
    if (t < 256) {
        int mat = t >> 7;            // 0 -> W1 (W_rel), 1 -> W2 (W_root)
        int k   = (t & 127) >> 1;    // feature row 0..63
        int o   = t & 1;             // output col 0..1
        const float* W = mat ? W_root : W_rel;
        float s = 0.f;
        #pragma unroll
        for (int j = 0; j < FEAT; ++j)
            s += W[k * FEAT + j] * W_pred[j * OUT_DIM + o];
        float* dstp = mat ? (float*)sW2 : (float*)sW1;
        dstp[k * 2 + o] = s;
    } else if (t < 256 + OUT_DIM) {
        int o = t - 256;
        float b = 0.f;
        #pragma unroll
        for (int j = 0; j < FEAT; ++j)
            b += b_rel[j] * W_pred[j * OUT_DIM + o];
        ((float*)&sbias)[o] = b + b_pred[o];
    }
    __syncthreads();

    // ---- node phase: warp = 4 nodes, 8-lane subgroups, float4 loads ----
    int warp = t >> 5;
    int lane = t & 31;
    int grp  = lane >> 3;            // 0..3  node within warp
    int q    = lane & 7;             // 0..7  feature quad within node

    int node = (blockIdx.x * 32 + warp) * 4 + grp;
    int ld   = node < N_NODES ? node : 0;

    float4 p = __ldcs((const float4*)(pos + ld * 32 + q * 4));
    float4 v = __ldcs((const float4*)(vel + ld * 32 + q * 4));

    float m0 = 0.f, m1 = 0.f, r0 = 0.f, r1 = 0.f;
    #pragma unroll
    for (int i = 0; i < 4; ++i) {
        float pe = (&p.x)[i];
        float ve = (&v.x)[i];
        int f = q * 4 + i;
        float2 w1p = sW1[f], w1v = sW1[32 + f];
        float2 w2p = sW2[f], w2v = sW2[32 + f];
        m0 += pe * w1p.x + ve * w1v.x;
        m1 += pe * w1p.y + ve * w1v.y;
        r0 += pe * w2p.x + ve * w2v.x;
        r1 += pe * w2p.y + ve * w2v.y;
    }
    #pragma unroll
    for (int off = 4; off > 0; off >>= 1) {
        m0 += __shfl_xor_sync(0xffffffffu, m0, off);
        m1 += __shfl_xor_sync(0xffffffffu, m1, off);
        r0 += __shfl_xor_sync(0xffffffffu, r0, off);
        r1 += __shfl_xor_sync(0xffffffffu, r1, off);
    }
    if (q == 0 && node < N_NODES) {
        g_m[node] = make_float2(m0, m1);
        ((float2*)out)[node] = make_float2(r0 + sbias.x, r1 + sbias.y);
    }
}

// ---------------------------------------------------------------------------
// Edge kernel: 8 edges/thread. out[dst] += m[src] via vector RED (L2 atomics).
// Index stream uses int4 + streaming hint (don't evict L2-resident m/out).
// ---------------------------------------------------------------------------
__device__ __forceinline__ void red_v2(float* addr, float2 v) {
    asm volatile("red.global.add.v2.f32 [%0], {%1, %2};"
                 :: "l"(addr), "f"(v.x), "f"(v.y) : "memory");
}

__global__ void edge_kernel(const int* __restrict__ src,
                            const int* __restrict__ dst,
                            float* __restrict__ out,
                            int n_edges) {
    int t = blockIdx.x * blockDim.x + threadIdx.x;
    int base = t * 8;
    if (base + 7 < n_edges) {
        int4 s0 = __ldcs((const int4*)(src + base));
        int4 s1 = __ldcs((const int4*)(src + base + 4));
        int4 d0 = __ldcs((const int4*)(dst + base));
        int4 d1 = __ldcs((const int4*)(dst + base + 4));
        float2 a0 = g_m[s0.x];
        float2 a1 = g_m[s0.y];
        float2 a2 = g_m[s0.z];
        float2 a3 = g_m[s0.w];
        float2 b0 = g_m[s1.x];
        float2 b1 = g_m[s1.y];
        float2 b2 = g_m[s1.z];
        float2 b3 = g_m[s1.w];
        red_v2(out + 2 * d0.x, a0);
        red_v2(out + 2 * d0.y, a1);
        red_v2(out + 2 * d0.z, a2);
        red_v2(out + 2 * d0.w, a3);
        red_v2(out + 2 * d1.x, b0);
        red_v2(out + 2 * d1.y, b1);
        red_v2(out + 2 * d1.z, b2);
        red_v2(out + 2 * d1.w, b3);
    } else {
        for (int i = base; i < n_edges; ++i) {
            float2 mm = g_m[src[i]];
            red_v2(out + 2 * dst[i], mm);
        }
    }
}

// ---------------------------------------------------------------------------
// Launch
// Inputs (metadata order): pos, vel, edge_index, W_rel, b_rel, W_root, W_pred, b_pred
// ---------------------------------------------------------------------------
extern "C" void kernel_launch(void* const* d_in, const int* in_sizes, int n_in,
                              void* d_out, int out_size) {
    const float* pos    = (const float*)d_in[0];
    const float* vel    = (const float*)d_in[1];
    const int*   eidx   = (const int*)  d_in[2];
    const float* W_rel  = (const float*)d_in[3];
    const float* b_rel  = (const float*)d_in[4];
    const float* W_root = (const float*)d_in[5];
    const float* W_pred = (const float*)d_in[6];
    const float* b_pred = (const float*)d_in[7];
    float* out = (float*)d_out;

    const int n_edges = in_sizes[2] / 2;          // 3.2M
    const int* src = eidx;
    const int* dst = eidx + n_edges;

    // 128 nodes per block (32 warps * 4 nodes)
    int n_blocks = (N_NODES + 127) / 128;
    node_kernel<<<n_blocks, 1024>>>(pos, vel, W_rel, b_rel, W_root,
                                    W_pred, b_pred, out);

    int n_thr = (n_edges + 7) / 8;
    edge_kernel<<<(n_thr + 255) / 256, 256>>>(src, dst, out, n_edges);
}

// round 4
// speedup vs baseline: 1.3465x; 1.3465x over previous
#include <cuda_runtime.h>
#include <cstdint>

#define N_NODES 100000
#define FEAT 64
#define OUT_DIM 2

// Folded weights: W1 = W_rel @ W_pred, W2 = W_root @ W_pred  (both [64][2])
// bias = b_rel @ W_pred + b_pred  ([2])
__device__ float g_W1[FEAT][OUT_DIM];
__device__ float g_W2[FEAT][OUT_DIM];
__device__ float g_bias[OUT_DIM];

// Per-node projected message m = h @ W1  (L2-resident: 800 KB)
__device__ float2 g_m[N_NODES];

// ---------------------------------------------------------------------------
// Kernel A: fold weights. One warp per output element (128 warps total).
// ---------------------------------------------------------------------------
__global__ void fold_weights_kernel(const float* __restrict__ W_rel,
                                    const float* __restrict__ b_rel,
                                    const float* __restrict__ W_root,
                                    const float* __restrict__ W_pred,
                                    const float* __restrict__ b_pred) {
    int w    = (blockIdx.x * blockDim.x + threadIdx.x) >> 5;  // 0..127
    int lane = threadIdx.x & 31;
    if (w >= FEAT * OUT_DIM) return;
    int k = w >> 1;        // row 0..63
    int o = w & 1;         // col 0..1
    int j0 = lane, j1 = lane + 32;

    float wp0 = W_pred[j0 * OUT_DIM + o];
    float wp1 = W_pred[j1 * OUT_DIM + o];
    float s1 = W_rel [k * FEAT + j0] * wp0 + W_rel [k * FEAT + j1] * wp1;
    float s2 = W_root[k * FEAT + j0] * wp0 + W_root[k * FEAT + j1] * wp1;
    float bb = (w < OUT_DIM) ? (b_rel[j0] * wp0 + b_rel[j1] * wp1) : 0.f;

    #pragma unroll
    for (int off = 16; off > 0; off >>= 1) {
        s1 += __shfl_xor_sync(0xffffffffu, s1, off);
        s2 += __shfl_xor_sync(0xffffffffu, s2, off);
        bb += __shfl_xor_sync(0xffffffffu, bb, off);
    }
    if (lane == 0) {
        g_W1[k][o] = s1;
        g_W2[k][o] = s2;
        if (w < OUT_DIM) g_bias[w] = bb + b_pred[w];
    }
}

// ---------------------------------------------------------------------------
// Kernel B: one warp per node (R2 version — 5us, near DRAM floor).
//   m[i]   = h[i] @ W1        (g_m)
//   out[i] = h[i] @ W2 + bias (root term initializes output)
// ---------------------------------------------------------------------------
__global__ void node_kernel(const float* __restrict__ pos,
                            const float* __restrict__ vel,
                            float* __restrict__ out) {
    int gwarp = (blockIdx.x * blockDim.x + threadIdx.x) >> 5;
    int lane  = threadIdx.x & 31;
    if (gwarp >= N_NODES) return;

    float p = __ldcs(pos + gwarp * 32 + lane);   // streaming, read-once
    float v = __ldcs(vel + gwarp * 32 + lane);

    float m0 = p * g_W1[lane][0] + v * g_W1[32 + lane][0];
    float m1 = p * g_W1[lane][1] + v * g_W1[32 + lane][1];
    float r0 = p * g_W2[lane][0] + v * g_W2[32 + lane][0];
    float r1 = p * g_W2[lane][1] + v * g_W2[32 + lane][1];

    #pragma unroll
    for (int off = 16; off > 0; off >>= 1) {
        m0 += __shfl_xor_sync(0xffffffffu, m0, off);
        m1 += __shfl_xor_sync(0xffffffffu, m1, off);
        r0 += __shfl_xor_sync(0xffffffffu, r0, off);
        r1 += __shfl_xor_sync(0xffffffffu, r1, off);
    }
    if (lane == 0) {
        g_m[gwarp] = make_float2(m0, m1);
        ((float2*)out)[gwarp] = make_float2(r0 + g_bias[0], r1 + g_bias[1]);
    }
}

// ---------------------------------------------------------------------------
// Kernel C: 16 edges/thread. out[dst] += m[src] via vector RED (L2 atomics).
// Index stream: int4 + streaming hint. Deep batching raises outstanding
// L2 requests per thread to push LTS saturation (was 66.5%).
// ---------------------------------------------------------------------------
__device__ __forceinline__ void red_v2(float* addr, float2 v) {
    asm volatile("red.global.add.v2.f32 [%0], {%1, %2};"
                 :: "l"(addr), "f"(v.x), "f"(v.y) : "memory");
}

__global__ void edge_kernel(const int* __restrict__ src,
                            const int* __restrict__ dst,
                            float* __restrict__ out,
                            int n_edges) {
    int t = blockIdx.x * blockDim.x + threadIdx.x;
    int base = t * 16;
    if (base + 15 < n_edges) {
        int4 s[4], d[4];
        #pragma unroll
        for (int i = 0; i < 4; ++i) {
            s[i] = __ldcs((const int4*)(src + base + 4 * i));
            d[i] = __ldcs((const int4*)(dst + base + 4 * i));
        }
        float2 m[16];
        #pragma unroll
        for (int i = 0; i < 4; ++i) {
            m[4 * i + 0] = g_m[s[i].x];
            m[4 * i + 1] = g_m[s[i].y];
            m[4 * i + 2] = g_m[s[i].z];
            m[4 * i + 3] = g_m[s[i].w];
        }
        #pragma unroll
        for (int i = 0; i < 4; ++i) {
            red_v2(out + 2 * d[i].x, m[4 * i + 0]);
            red_v2(out + 2 * d[i].y, m[4 * i + 1]);
            red_v2(out + 2 * d[i].z, m[4 * i + 2]);
            red_v2(out + 2 * d[i].w, m[4 * i + 3]);
        }
    } else {
        for (int i = base; i < n_edges; ++i) {
            float2 mm = g_m[src[i]];
            red_v2(out + 2 * dst[i], mm);
        }
    }
}

// ---------------------------------------------------------------------------
// Launch
// Inputs (metadata order): pos, vel, edge_index, W_rel, b_rel, W_root, W_pred, b_pred
// ---------------------------------------------------------------------------
extern "C" void kernel_launch(void* const* d_in, const int* in_sizes, int n_in,
                              void* d_out, int out_size) {
    const float* pos    = (const float*)d_in[0];
    const float* vel    = (const float*)d_in[1];
    const int*   eidx   = (const int*)  d_in[2];
    const float* W_rel  = (const float*)d_in[3];
    const float* b_rel  = (const float*)d_in[4];
    const float* W_root = (const float*)d_in[5];
    const float* W_pred = (const float*)d_in[6];
    const float* b_pred = (const float*)d_in[7];
    float* out = (float*)d_out;

    const int n_edges = in_sizes[2] / 2;          // 3.2M
    const int* src = eidx;
    const int* dst = eidx + n_edges;

    fold_weights_kernel<<<4, 1024>>>(W_rel, b_rel, W_root, W_pred, b_pred);

    node_kernel<<<(N_NODES * 32 + 1023) / 1024, 1024>>>(pos, vel, out);

    int n_thr = (n_edges + 15) / 16;
    edge_kernel<<<(n_thr + 255) / 256, 256>>>(src, dst, out, n_edges);
}

// round 5
// speedup vs baseline: 1.4807x; 1.0997x over previous
#include <cuda_runtime.h>
#include <cstdint>

#define N_NODES 100000
#define FEAT 64
#define OUT_DIM 2

// Per-node projected message m = h @ W1  (L2-resident: 800 KB)
__device__ float2 g_m[N_NODES];

// ---------------------------------------------------------------------------
// Fused node kernel: warp-cooperative per-block weight fold (coalesced loads,
// butterfly reduce — NOT the scalar-strided R3 disaster), then warp-per-node
// projection with a warp-stride loop.
//   W1 = W_rel @ W_pred, W2 = W_root @ W_pred, bias = b_rel@W_pred + b_pred
//   m[i]   = h[i] @ W1        (g_m)
//   out[i] = h[i] @ W2 + bias
// Grid: 296 blocks x 1024 threads (2 resident blocks/SM, full occupancy).
// ---------------------------------------------------------------------------
__global__ __launch_bounds__(1024, 2)
void node_kernel(const float* __restrict__ pos,
                 const float* __restrict__ vel,
                 const float* __restrict__ W_rel,
                 const float* __restrict__ b_rel,
                 const float* __restrict__ W_root,
                 const float* __restrict__ W_pred,
                 const float* __restrict__ b_pred,
                 float* __restrict__ out) {
    __shared__ float sW1[FEAT][OUT_DIM];
    __shared__ float sW2[FEAT][OUT_DIM];
    __shared__ float sbias[OUT_DIM];

    int t    = threadIdx.x;
    int warp = t >> 5;            // 0..31
    int lane = t & 31;

    // ---- fold phase: 32 warps x 4 (k,o)-pairs = 128 folded entries ----
    #pragma unroll
    for (int i = 0; i < 4; ++i) {
        int p = warp * 4 + i;     // 0..127
        int k = p >> 1;           // row 0..63
        int o = p & 1;            // col 0..1
        float wp0 = W_pred[lane * OUT_DIM + o];
        float wp1 = W_pred[(lane + 32) * OUT_DIM + o];
        float s1 = W_rel [k * FEAT + lane] * wp0 + W_rel [k * FEAT + lane + 32] * wp1;
        float s2 = W_root[k * FEAT + lane] * wp0 + W_root[k * FEAT + lane + 32] * wp1;
        #pragma unroll
        for (int off = 16; off > 0; off >>= 1) {
            s1 += __shfl_xor_sync(0xffffffffu, s1, off);
            s2 += __shfl_xor_sync(0xffffffffu, s2, off);
        }
        if (lane == 0) { sW1[k][o] = s1; sW2[k][o] = s2; }
    }
    if (warp < OUT_DIM) {         // warps 0,1 compute the bias
        int o = warp;
        float bb = b_rel[lane]      * W_pred[lane * OUT_DIM + o]
                 + b_rel[lane + 32] * W_pred[(lane + 32) * OUT_DIM + o];
        #pragma unroll
        for (int off = 16; off > 0; off >>= 1)
            bb += __shfl_xor_sync(0xffffffffu, bb, off);
        if (lane == 0) sbias[o] = bb + b_pred[o];
    }
    __syncthreads();

    // per-lane folded weights (registers, read once from smem)
    float w1p0 = sW1[lane][0],      w1p1 = sW1[lane][1];
    float w1v0 = sW1[lane + 32][0], w1v1 = sW1[lane + 32][1];
    float w2p0 = sW2[lane][0],      w2p1 = sW2[lane][1];
    float w2v0 = sW2[lane + 32][0], w2v1 = sW2[lane + 32][1];
    float bias0 = sbias[0], bias1 = sbias[1];

    // ---- node phase: warp per node, warp-stride loop ----
    int warp_g      = blockIdx.x * 32 + warp;
    int total_warps = gridDim.x * 32;

    for (int node = warp_g; node < N_NODES; node += total_warps) {
        float p = __ldcs(pos + node * 32 + lane);   // coalesced 128B
        float v = __ldcs(vel + node * 32 + lane);

        float m0 = p * w1p0 + v * w1v0;
        float m1 = p * w1p1 + v * w1v1;
        float r0 = p * w2p0 + v * w2v0;
        float r1 = p * w2p1 + v * w2v1;

        #pragma unroll
        for (int off = 16; off > 0; off >>= 1) {
            m0 += __shfl_xor_sync(0xffffffffu, m0, off);
            m1 += __shfl_xor_sync(0xffffffffu, m1, off);
            r0 += __shfl_xor_sync(0xffffffffu, r0, off);
            r1 += __shfl_xor_sync(0xffffffffu, r1, off);
        }
        if (lane == 0) {
            g_m[node] = make_float2(m0, m1);
            ((float2*)out)[node] = make_float2(r0 + bias0, r1 + bias1);
        }
    }
}

// ---------------------------------------------------------------------------
// Edge kernel: 8 edges per iteration, grid-stride with exactly one resident
// wave (1184 blocks x 256 thr) to eliminate the wave-quantization tail.
// out[dst] += m[src] via vector RED (L2 atomics); int4 streaming index loads.
// ---------------------------------------------------------------------------
__device__ __forceinline__ void red_v2(float* addr, float2 v) {
    asm volatile("red.global.add.v2.f32 [%0], {%1, %2};"
                 :: "l"(addr), "f"(v.x), "f"(v.y) : "memory");
}

__global__ void edge_kernel(const int* __restrict__ src,
                            const int* __restrict__ dst,
                            float* __restrict__ out,
                            int n_edges) {
    int tid      = blockIdx.x * blockDim.x + threadIdx.x;
    int nthreads = gridDim.x * blockDim.x;
    int n8       = n_edges & ~7;

    for (int base = tid * 8; base + 7 < n_edges; base += nthreads * 8) {
        int4 s0 = __ldcs((const int4*)(src + base));
        int4 s1 = __ldcs((const int4*)(src + base + 4));
        int4 d0 = __ldcs((const int4*)(dst + base));
        int4 d1 = __ldcs((const int4*)(dst + base + 4));
        float2 a0 = g_m[s0.x];
        float2 a1 = g_m[s0.y];
        float2 a2 = g_m[s0.z];
        float2 a3 = g_m[s0.w];
        float2 b0 = g_m[s1.x];
        float2 b1 = g_m[s1.y];
        float2 b2 = g_m[s1.z];
        float2 b3 = g_m[s1.w];
        red_v2(out + 2 * d0.x, a0);
        red_v2(out + 2 * d0.y, a1);
        red_v2(out + 2 * d0.z, a2);
        red_v2(out + 2 * d0.w, a3);
        red_v2(out + 2 * d1.x, b0);
        red_v2(out + 2 * d1.y, b1);
        red_v2(out + 2 * d1.z, b2);
        red_v2(out + 2 * d1.w, b3);
    }
    // tail (n_edges not multiple of 8): one thread mops up <=7 edges
    if (tid == 0) {
        for (int i = n8; i < n_edges; ++i) {
            float2 mm = g_m[src[i]];
            red_v2(out + 2 * dst[i], mm);
        }
    }
}

// ---------------------------------------------------------------------------
// Launch
// Inputs (metadata order): pos, vel, edge_index, W_rel, b_rel, W_root, W_pred, b_pred
// ---------------------------------------------------------------------------
extern "C" void kernel_launch(void* const* d_in, const int* in_sizes, int n_in,
                              void* d_out, int out_size) {
    const float* pos    = (const float*)d_in[0];
    const float* vel    = (const float*)d_in[1];
    const int*   eidx   = (const int*)  d_in[2];
    const float* W_rel  = (const float*)d_in[3];
    const float* b_rel  = (const float*)d_in[4];
    const float* W_root = (const float*)d_in[5];
    const float* W_pred = (const float*)d_in[6];
    const float* b_pred = (const float*)d_in[7];
    float* out = (float*)d_out;

    const int n_edges = in_sizes[2] / 2;          // 3.2M
    const int* src = eidx;
    const int* dst = eidx + n_edges;

    node_kernel<<<296, 1024>>>(pos, vel, W_rel, b_rel, W_root,
                               W_pred, b_pred, out);

    edge_kernel<<<1184, 256>>>(src, dst, out, n_edges);
}